// round 9
// baseline (speedup 1.0000x reference)
#include <cuda_runtime.h>
#include <cuda_bf16.h>
#include <math.h>
#include <stdint.h>

// Problem constants (fixed by the dataset)
#define NN    50000
#define NE    400000
#define NETOT (NE + NN)   // with self loops
#define DIN   128
#define HID   32
#define HEADS 8
#define F1    (HEADS * HID)   // 256
#define OUTF  16
#define NEG_SLOPE 0.2f

// ---------------- static device scratch (no allocations allowed) -------------
__device__ float g_xl1[NN * F1];
__device__ float g_xr1[NN * F1];
__device__ float g_h1 [NN * F1];
__device__ float g_xl2[NN * HID];
__device__ float g_xr2[NN * HID];
__device__ int   g_deg[NN];
__device__ int   g_rowptr[NN + 1];
__device__ int   g_cursor[NN];
__device__ int   g_csrsrc[NETOT];

// ---------------- CSR construction ------------------------------------------
__global__ void zero_deg_kernel(int n) {
    int i = blockIdx.x * blockDim.x + threadIdx.x;
    if (i < n) g_deg[i] = 0;
}

__global__ void hist_kernel(const int* __restrict__ ei, int E, int n) {
    int e = blockIdx.x * blockDim.x + threadIdx.x;
    int etot = E + n;
    if (e >= etot) return;
    int dst = (e < E) ? ei[E + e] : (e - E);
    if ((unsigned)dst < (unsigned)n) atomicAdd(&g_deg[dst], 1);
}

// single-block exclusive scan, int4 per thread per iteration
__global__ void scan_kernel(int n) {
    __shared__ int wsum[32];
    int tid  = threadIdx.x;          // blockDim.x == 1024
    int lane = tid & 31, wid = tid >> 5;
    int carry = 0;
    for (int base = 0; base < n; base += 4096) {
        int i0 = base + tid * 4;
        int4 v = make_int4(0, 0, 0, 0);
        if (i0 < n) v = *(const int4*)&g_deg[i0];
        int s1 = v.x + v.y;
        int s2 = s1 + v.z;
        int tot = s2 + v.w;
        int x = tot;
        #pragma unroll
        for (int o = 1; o < 32; o <<= 1) {
            int y = __shfl_up_sync(0xffffffffu, x, o);
            if (lane >= o) x += y;
        }
        if (lane == 31) wsum[wid] = x;
        __syncthreads();
        if (wid == 0) {
            int s = wsum[lane];
            #pragma unroll
            for (int o = 1; o < 32; o <<= 1) {
                int y = __shfl_up_sync(0xffffffffu, s, o);
                if (lane >= o) s += y;
            }
            wsum[lane] = s;
        }
        __syncthreads();
        int wprefix = wid ? wsum[wid - 1] : 0;
        int excl = carry + wprefix + (x - tot);
        if (i0 < n) {
            int4 w = make_int4(excl, excl + v.x, excl + s1, excl + s2);
            *(int4*)&g_rowptr[i0] = w;
            *(int4*)&g_cursor[i0] = w;
        }
        carry += wsum[31];
        __syncthreads();
    }
    if (tid == 0) g_rowptr[n] = carry;
}

__global__ void scatter_kernel(const int* __restrict__ ei, int E, int n) {
    int e = blockIdx.x * blockDim.x + threadIdx.x;
    int etot = E + n;
    if (e >= etot) return;
    int src, dst;
    if (e < E) { src = ei[e]; dst = ei[E + e]; }
    else       { src = e - E; dst = e - E; }
    if ((unsigned)dst >= (unsigned)n || (unsigned)src >= (unsigned)n) return;
    int pos = atomicAdd(&g_cursor[dst], 1);
    if (pos < NETOT) g_csrsrc[pos] = src;
}

// ---------------- tf32 tensor-core GEMMs -------------------------------------
__device__ __forceinline__ uint32_t f2tf32(float x) {
    uint32_t r;
    asm("cvt.rna.tf32.f32 %0, %1;" : "=r"(r) : "f"(x));
    return r;
}

__device__ __forceinline__ void mma_tf32(float c[4], const uint32_t a[4],
                                         const uint32_t b[2]) {
    asm volatile(
        "mma.sync.aligned.m16n8k8.row.col.f32.tf32.tf32.f32 "
        "{%0,%1,%2,%3}, {%4,%5,%6,%7}, {%8,%9}, {%0,%1,%2,%3};"
        : "+f"(c[0]), "+f"(c[1]), "+f"(c[2]), "+f"(c[3])
        : "r"(a[0]), "r"(a[1]), "r"(a[2]), "r"(a[3]), "r"(b[0]), "r"(b[1]));
}

// LAYER 1: A = x [M,128], B(z) = W1l/W1r [128,256], C(z) = g_xl1/g_xr1
// 128x128 block tile, 64x32 warp tile (MT=4, NT=4). SMEM holds tf32 bits
// (converted at store) in the conflict-free scalar layout.
__global__ void __launch_bounds__(256, 2)
tf32_gemm1_kernel(const float* __restrict__ A,
                  const float* __restrict__ Bl,
                  const float* __restrict__ Br, int M) {
    constexpr int K = DIN, N = F1;
    constexpr int BM = 128, BN = 128, BK = 32;
    constexpr int MT = 4, NT = 4, WN = 4;
    constexpr int AS = BK + 4;    // 36 u32: bank = 4*row + k (all distinct)
    constexpr int BS = BN + 8;    // 136 u32: 136 % 32 == 8 -> bank = 8*k + col

    __shared__ uint32_t As[BM][AS];
    __shared__ uint32_t Bs[BK][BS];

    const float* __restrict__ B = blockIdx.z ? Br : Bl;
    float* __restrict__ C = blockIdx.z ? g_xr1 : g_xl1;

    const int bm = blockIdx.y * BM;
    const int bn = blockIdx.x * BN;
    const int tid  = threadIdx.x;
    const int wid  = tid >> 5;
    const int lane = tid & 31;
    const int wm = (wid / WN) * (MT * 16);   // 0 or 64
    const int wn = (wid % WN) * (NT * 8);    // 0,32,64,96
    const int lr = lane >> 2, lc = lane & 3;

    float c[MT][NT][4];
    #pragma unroll
    for (int i = 0; i < MT; i++)
        #pragma unroll
        for (int j = 0; j < NT; j++)
            #pragma unroll
            for (int q = 0; q < 4; q++) c[i][j][q] = 0.f;

    for (int k0 = 0; k0 < K; k0 += BK) {
        #pragma unroll
        for (int f = tid; f < BM * (BK / 4); f += 256) {
            int r = f >> 3, cv = (f & 7) * 4;
            int gr = bm + r;
            float4 v = (gr < M)
                ? *(const float4*)&A[(size_t)gr * K + k0 + cv]
                : make_float4(0.f, 0.f, 0.f, 0.f);
            As[r][cv]     = f2tf32(v.x);
            As[r][cv + 1] = f2tf32(v.y);
            As[r][cv + 2] = f2tf32(v.z);
            As[r][cv + 3] = f2tf32(v.w);
        }
        #pragma unroll
        for (int f = tid; f < BK * (BN / 4); f += 256) {
            int r = f / (BN / 4), cv = (f % (BN / 4)) * 4;
            float4 v = *(const float4*)&B[(size_t)(k0 + r) * N + bn + cv];
            Bs[r][cv]     = f2tf32(v.x);
            Bs[r][cv + 1] = f2tf32(v.y);
            Bs[r][cv + 2] = f2tf32(v.z);
            Bs[r][cv + 3] = f2tf32(v.w);
        }
        __syncthreads();
        #pragma unroll
        for (int kk = 0; kk < BK; kk += 8) {
            uint32_t af[MT][4], bf[NT][2];
            #pragma unroll
            for (int mt = 0; mt < MT; mt++) {
                int row = wm + mt * 16 + lr;
                int cA = kk + lc;
                af[mt][0] = As[row][cA];
                af[mt][1] = As[row + 8][cA];
                af[mt][2] = As[row][cA + 4];
                af[mt][3] = As[row + 8][cA + 4];
            }
            #pragma unroll
            for (int nt = 0; nt < NT; nt++) {
                int col = wn + nt * 8 + lr;
                bf[nt][0] = Bs[kk + lc][col];
                bf[nt][1] = Bs[kk + lc + 4][col];
            }
            #pragma unroll
            for (int mt = 0; mt < MT; mt++)
                #pragma unroll
                for (int nt = 0; nt < NT; nt++)
                    mma_tf32(c[mt][nt], af[mt], bf[nt]);
        }
        __syncthreads();
    }
    #pragma unroll
    for (int mt = 0; mt < MT; mt++) {
        int r0 = bm + wm + mt * 16 + lr;
        int r1 = r0 + 8;
        #pragma unroll
        for (int nt = 0; nt < NT; nt++) {
            int cn = bn + wn + nt * 8 + lc * 2;
            if (r0 < M)
                *(float2*)&C[(size_t)r0 * N + cn] = make_float2(c[mt][nt][0], c[mt][nt][1]);
            if (r1 < M)
                *(float2*)&C[(size_t)r1 * N + cn] = make_float2(c[mt][nt][2], c[mt][nt][3]);
        }
    }
}

// LAYER 2 fused: A = g_h1 [M,256]; computes BOTH xl2 and xr2 in one pass.
__global__ void __launch_bounds__(256)
tf32_gemm2_kernel(const float* __restrict__ Bl,
                  const float* __restrict__ Br, int M) {
    constexpr int K = F1, N = HID;
    constexpr int BM = 128, BK = 32;
    constexpr int NT = 4;
    constexpr int AS = BK + 4;   // 36
    constexpr int BS = N + 8;    // 40

    __shared__ uint32_t As [BM][AS];
    __shared__ uint32_t Bsl[BK][BS];
    __shared__ uint32_t Bsr[BK][BS];

    const float* __restrict__ A = (const float*)g_h1;
    const int bm = blockIdx.y * BM;
    const int tid  = threadIdx.x;
    const int wid  = tid >> 5;
    const int lane = tid & 31;
    const int wm = wid * 16;
    const int lr = lane >> 2, lc = lane & 3;

    float cl[NT][4], cr[NT][4];
    #pragma unroll
    for (int j = 0; j < NT; j++)
        #pragma unroll
        for (int q = 0; q < 4; q++) { cl[j][q] = 0.f; cr[j][q] = 0.f; }

    for (int k0 = 0; k0 < K; k0 += BK) {
        #pragma unroll
        for (int f = tid; f < BM * (BK / 4); f += 256) {
            int r = f >> 3, cv = (f & 7) * 4;
            int gr = bm + r;
            float4 v = (gr < M)
                ? *(const float4*)&A[(size_t)gr * K + k0 + cv]
                : make_float4(0.f, 0.f, 0.f, 0.f);
            As[r][cv]     = f2tf32(v.x);
            As[r][cv + 1] = f2tf32(v.y);
            As[r][cv + 2] = f2tf32(v.z);
            As[r][cv + 3] = f2tf32(v.w);
        }
        #pragma unroll
        for (int f = tid; f < BK * (N / 4); f += 256) {
            int r = f / (N / 4), cv = (f % (N / 4)) * 4;
            float4 vl = *(const float4*)&Bl[(size_t)(k0 + r) * N + cv];
            float4 vr = *(const float4*)&Br[(size_t)(k0 + r) * N + cv];
            Bsl[r][cv]     = f2tf32(vl.x);
            Bsl[r][cv + 1] = f2tf32(vl.y);
            Bsl[r][cv + 2] = f2tf32(vl.z);
            Bsl[r][cv + 3] = f2tf32(vl.w);
            Bsr[r][cv]     = f2tf32(vr.x);
            Bsr[r][cv + 1] = f2tf32(vr.y);
            Bsr[r][cv + 2] = f2tf32(vr.z);
            Bsr[r][cv + 3] = f2tf32(vr.w);
        }
        __syncthreads();
        #pragma unroll
        for (int kk = 0; kk < BK; kk += 8) {
            uint32_t af[4], bfl[NT][2], bfr[NT][2];
            {
                int row = wm + lr;
                int cA = kk + lc;
                af[0] = As[row][cA];
                af[1] = As[row + 8][cA];
                af[2] = As[row][cA + 4];
                af[3] = As[row + 8][cA + 4];
            }
            #pragma unroll
            for (int nt = 0; nt < NT; nt++) {
                int col = nt * 8 + lr;
                bfl[nt][0] = Bsl[kk + lc][col];
                bfl[nt][1] = Bsl[kk + lc + 4][col];
                bfr[nt][0] = Bsr[kk + lc][col];
                bfr[nt][1] = Bsr[kk + lc + 4][col];
            }
            #pragma unroll
            for (int nt = 0; nt < NT; nt++) {
                mma_tf32(cl[nt], af, bfl[nt]);
                mma_tf32(cr[nt], af, bfr[nt]);
            }
        }
        __syncthreads();
    }
    int r0 = bm + wm + lr;
    int r1 = r0 + 8;
    #pragma unroll
    for (int nt = 0; nt < NT; nt++) {
        int cn = nt * 8 + lc * 2;
        if (r0 < M) {
            *(float2*)&g_xl2[(size_t)r0 * N + cn] = make_float2(cl[nt][0], cl[nt][1]);
            *(float2*)&g_xr2[(size_t)r0 * N + cn] = make_float2(cr[nt][0], cr[nt][1]);
        }
        if (r1 < M) {
            *(float2*)&g_xl2[(size_t)r1 * N + cn] = make_float2(cl[nt][2], cl[nt][3]);
            *(float2*)&g_xr2[(size_t)r1 * N + cn] = make_float2(cr[nt][2], cr[nt][3]);
        }
    }
}

// ---------------- layer-1 edge pass: segment softmax + aggregate -------------
__device__ __forceinline__ void gat1_accum(const float4& a, const float4& b,
                                           const float xr[8], const float att[8],
                                           float acc[8], float& den) {
    float xl[8] = {a.x, a.y, a.z, a.w, b.x, b.y, b.z, b.w};
    float p = 0.f;
    #pragma unroll
    for (int i = 0; i < 8; i++) {
        float s = xl[i] + xr[i];
        s = s > 0.f ? s : NEG_SLOPE * s;
        p += s * att[i];
    }
    p += __shfl_xor_sync(0xffffffffu, p, 1);
    p += __shfl_xor_sync(0xffffffffu, p, 2);
    float w = __expf(p);
    den += w;
    #pragma unroll
    for (int i = 0; i < 8; i++) acc[i] += w * xl[i];
}

__global__ void gat1_edge_kernel(const float* __restrict__ att1,
                                 const float* __restrict__ b1, int n) {
    int warp_id = (blockIdx.x * blockDim.x + threadIdx.x) >> 5;
    if (warp_id >= n) return;
    int lane = threadIdx.x & 31;
    int dst  = warp_id;
    int base = (lane >> 2) * 32 + (lane & 3) * 8;  // head*32 + quarter*8

    float xr[8], att[8], acc[8];
    {
        const float4* p0 = (const float4*)&g_xr1[dst * F1 + base];
        float4 a = p0[0], b = p0[1];
        xr[0]=a.x; xr[1]=a.y; xr[2]=a.z; xr[3]=a.w;
        xr[4]=b.x; xr[5]=b.y; xr[6]=b.z; xr[7]=b.w;
        const float4* p1 = (const float4*)&att1[base];
        float4 c = p1[0], d4 = p1[1];
        att[0]=c.x; att[1]=c.y; att[2]=c.z; att[3]=c.w;
        att[4]=d4.x; att[5]=d4.y; att[6]=d4.z; att[7]=d4.w;
    }
    #pragma unroll
    for (int i = 0; i < 8; i++) acc[i] = 0.f;
    float den = 0.f;

    int beg = g_rowptr[dst], end = g_rowptr[dst + 1];
    int e = beg;
    // 4-way unrolled gather: 8 outstanding LDG.128 per lane
    for (; e + 4 <= end; e += 4) {
        int s0 = g_csrsrc[e];
        int s1 = g_csrsrc[e + 1];
        int s2 = g_csrsrc[e + 2];
        int s3 = g_csrsrc[e + 3];
        const float4* p0 = (const float4*)&g_xl1[s0 * F1 + base];
        const float4* p1 = (const float4*)&g_xl1[s1 * F1 + base];
        const float4* p2 = (const float4*)&g_xl1[s2 * F1 + base];
        const float4* p3 = (const float4*)&g_xl1[s3 * F1 + base];
        float4 a0 = p0[0], b0 = p0[1];
        float4 a1 = p1[0], b1v = p1[1];
        float4 a2 = p2[0], b2v = p2[1];
        float4 a3 = p3[0], b3v = p3[1];
        gat1_accum(a0, b0, xr, att, acc, den);
        gat1_accum(a1, b1v, xr, att, acc, den);
        gat1_accum(a2, b2v, xr, att, acc, den);
        gat1_accum(a3, b3v, xr, att, acc, den);
    }
    for (; e < end; e++) {
        int s0 = g_csrsrc[e];
        const float4* p0 = (const float4*)&g_xl1[s0 * F1 + base];
        float4 a0 = p0[0], b0 = p0[1];
        gat1_accum(a0, b0, xr, att, acc, den);
    }

    float inv = 1.f / fmaxf(den, 1e-16f);
    const float4* pb = (const float4*)&b1[base];
    float4 bb0 = pb[0], bb1 = pb[1];
    float bb[8] = {bb0.x, bb0.y, bb0.z, bb0.w, bb1.x, bb1.y, bb1.z, bb1.w};
    float o[8];
    #pragma unroll
    for (int i = 0; i < 8; i++) {
        float v = acc[i] * inv + bb[i];
        o[i] = v > 0.f ? v : (__expf(v) - 1.f);   // ELU
    }
    float4* po = (float4*)&g_h1[dst * F1 + base];
    po[0] = make_float4(o[0], o[1], o[2], o[3]);
    po[1] = make_float4(o[4], o[5], o[6], o[7]);
}

// ---------------- layer-2 edge pass + ELU + fused final linear ---------------
__global__ void gat2_edge_kernel(const float* __restrict__ att2,
                                 const float* __restrict__ b2,
                                 const float* __restrict__ Wlin,
                                 const float* __restrict__ blin,
                                 float* __restrict__ out, int n) {
    __shared__ float sh[8 * 32];
    int warp_id = (blockIdx.x * blockDim.x + threadIdx.x) >> 5;
    if (warp_id >= n) return;
    int lane = threadIdx.x & 31;
    int wib  = (threadIdx.x >> 5);
    int dst = warp_id;

    float xr = g_xr2[dst * HID + lane];
    float a  = att2[lane];
    float den = 0.f, acc = 0.f;

    int beg = g_rowptr[dst], end = g_rowptr[dst + 1];
    for (int e = beg; e < end; e++) {
        int src = g_csrsrc[e];
        float xl = g_xl2[src * HID + lane];
        float s = xl + xr;
        s = s > 0.f ? s : NEG_SLOPE * s;
        float p = s * a;
        #pragma unroll
        for (int o = 16; o > 0; o >>= 1)
            p += __shfl_xor_sync(0xffffffffu, p, o);
        float w = __expf(p);
        den += w;
        acc += w * xl;
    }
    float o = acc / fmaxf(den, 1e-16f) + b2[lane];
    float hv = o > 0.f ? o : (__expf(o) - 1.f);   // ELU
    sh[wib * 32 + lane] = hv;
    __syncwarp();
    if (lane < OUTF) {
        float s = blin[lane];
        #pragma unroll
        for (int c = 0; c < HID; c++)
            s += sh[wib * 32 + c] * Wlin[c * OUTF + lane];
        out[dst * OUTF + lane] = s;
    }
}

// ---------------- launch ------------------------------------------------------
extern "C" void kernel_launch(void* const* d_in, const int* in_sizes, int n_in,
                              void* d_out, int out_size) {
    const float* x    = (const float*)d_in[0];
    const int*   ei   = (const int*)d_in[1];     // int32 on device
    const float* W1l  = (const float*)d_in[2];
    const float* W1r  = (const float*)d_in[3];
    const float* att1 = (const float*)d_in[4];
    const float* b1   = (const float*)d_in[5];
    const float* W2l  = (const float*)d_in[6];
    const float* W2r  = (const float*)d_in[7];
    const float* att2 = (const float*)d_in[8];
    const float* b2   = (const float*)d_in[9];
    const float* Wlin = (const float*)d_in[10];
    const float* blin = (const float*)d_in[11];
    float*       out  = (float*)d_out;

    const int n = in_sizes[0] / DIN;        // 50000
    const int E = in_sizes[1] / 2;          // 400000
    const int etot = E + n;

    // Fork-join stream for overlapping gemm1 with the CSR build.
    // Host-side objects only (no device memory); created once, reused so the
    // captured graph is identical on every call.
    static cudaStream_t s_side = nullptr;
    static cudaEvent_t  ev_fork = nullptr, ev_join = nullptr;
    if (s_side == nullptr) {
        cudaStreamCreateWithFlags(&s_side, cudaStreamNonBlocking);
        cudaEventCreateWithFlags(&ev_fork, cudaEventDisableTiming);
        cudaEventCreateWithFlags(&ev_join, cudaEventDisableTiming);
    }

    // fork point: gemm1 depends only on inputs
    cudaEventRecord(ev_fork, 0);

    // main stream: CSR build chain
    zero_deg_kernel<<<(n + 255) / 256, 256>>>(n);                 // k1
    hist_kernel<<<(etot + 255) / 256, 256>>>(ei, E, n);           // k2
    scan_kernel<<<1, 1024>>>(n);                                  // k3

    // side stream: layer-1 GEMMs run concurrently with CSR build
    cudaStreamWaitEvent(s_side, ev_fork, 0);
    {
        dim3 grid(F1 / 128, (n + 127) / 128, 2);
        tf32_gemm1_kernel<<<grid, 256, 0, s_side>>>(x, W1l, W1r, n); // k4 (profiled)
    }
    cudaEventRecord(ev_join, s_side);

    scatter_kernel<<<(etot + 255) / 256, 256>>>(ei, E, n);        // k5

    // join: edge1 needs both CSR and gemm1 results
    cudaStreamWaitEvent(0, ev_join, 0);

    gat1_edge_kernel<<<(n * 32 + 255) / 256, 256>>>(att1, b1, n); // k6

    {
        dim3 grid(1, (n + 127) / 128);
        tf32_gemm2_kernel<<<grid, 256>>>(W2l, W2r, n);            // k7
    }

    gat2_edge_kernel<<<(n * 32 + 255) / 256, 256>>>(att2, b2, Wlin, blin, out, n); // k8
}

// round 10
// speedup vs baseline: 1.0117x; 1.0117x over previous
#include <cuda_runtime.h>
#include <cuda_bf16.h>
#include <math.h>
#include <stdint.h>

// Problem constants (fixed by the dataset)
#define NN    50000
#define NE    400000
#define NETOT (NE + NN)   // with self loops
#define DIN   128
#define HID   32
#define HEADS 8
#define F1    (HEADS * HID)   // 256
#define OUTF  16
#define NEG_SLOPE 0.2f

// ---------------- static device scratch (no allocations allowed) -------------
__device__ float    g_xl1[NN * F1];
__device__ float    g_xr1[NN * F1];
__device__ float    g_h1 [NN * F1];   // doubles as tf32(x) scratch before edge1
__device__ float    g_xl2[NN * HID];
__device__ float    g_xr2[NN * HID];
__device__ uint32_t g_w1tf[2][DIN * F1];   // tf32 bits of W1l / W1r
__device__ int      g_deg[NN];
__device__ int      g_rowptr[NN + 1];
__device__ int      g_cursor[NN];
__device__ int      g_csrsrc[NETOT];

// ---------------- tf32 helpers -----------------------------------------------
__device__ __forceinline__ uint32_t f2tf32(float x) {
    uint32_t r;
    asm("cvt.rna.tf32.f32 %0, %1;" : "=r"(r) : "f"(x));
    return r;
}

__device__ __forceinline__ void mma_tf32(float c[4], const uint32_t a[4],
                                         const uint32_t b[2]) {
    asm volatile(
        "mma.sync.aligned.m16n8k8.row.col.f32.tf32.tf32.f32 "
        "{%0,%1,%2,%3}, {%4,%5,%6,%7}, {%8,%9}, {%0,%1,%2,%3};"
        : "+f"(c[0]), "+f"(c[1]), "+f"(c[2]), "+f"(c[3])
        : "r"(a[0]), "r"(a[1]), "r"(a[2]), "r"(a[3]), "r"(b[0]), "r"(b[1]));
}

__device__ __forceinline__ void cp_async16(uint32_t dst_smem, const void* src) {
    asm volatile("cp.async.cg.shared.global [%0], [%1], 16;"
                 :: "r"(dst_smem), "l"(src));
}

// ---------------- input pre-conversion to tf32 -------------------------------
// tf32(W1l) -> g_w1tf[0], tf32(W1r) -> g_w1tf[1]
__global__ void cvt_w_kernel(const float* __restrict__ Wl,
                             const float* __restrict__ Wr) {
    int i = blockIdx.x * blockDim.x + threadIdx.x;   // uint4 index, 2*8192 total
    int m = i >> 13;
    int j = i & 8191;
    const float4* src = (const float4*)(m ? Wr : Wl);
    float4 v = src[j];
    ((uint4*)g_w1tf[m])[j] =
        make_uint4(f2tf32(v.x), f2tf32(v.y), f2tf32(v.z), f2tf32(v.w));
}

// tf32(x) -> first n*DIN words of g_h1 (dead until edge1 overwrites it)
__global__ void cvt_x_kernel(const float* __restrict__ x, int count4) {
    int i = blockIdx.x * blockDim.x + threadIdx.x;
    if (i >= count4) return;
    float4 v = ((const float4*)x)[i];
    ((uint4*)g_h1)[i] =
        make_uint4(f2tf32(v.x), f2tf32(v.y), f2tf32(v.z), f2tf32(v.w));
}

// ---------------- CSR construction ------------------------------------------
__global__ void zero_deg_kernel(int n) {
    int i = blockIdx.x * blockDim.x + threadIdx.x;
    if (i < n) g_deg[i] = 0;
}

__global__ void hist_kernel(const int* __restrict__ ei, int E, int n) {
    int e = blockIdx.x * blockDim.x + threadIdx.x;
    int etot = E + n;
    if (e >= etot) return;
    int dst = (e < E) ? ei[E + e] : (e - E);
    if ((unsigned)dst < (unsigned)n) atomicAdd(&g_deg[dst], 1);
}

// single-block exclusive scan, int4 per thread per iteration
__global__ void scan_kernel(int n) {
    __shared__ int wsum[32];
    int tid  = threadIdx.x;          // blockDim.x == 1024
    int lane = tid & 31, wid = tid >> 5;
    int carry = 0;
    for (int base = 0; base < n; base += 4096) {
        int i0 = base + tid * 4;
        int4 v = make_int4(0, 0, 0, 0);
        if (i0 < n) v = *(const int4*)&g_deg[i0];
        int s1 = v.x + v.y;
        int s2 = s1 + v.z;
        int tot = s2 + v.w;
        int x = tot;
        #pragma unroll
        for (int o = 1; o < 32; o <<= 1) {
            int y = __shfl_up_sync(0xffffffffu, x, o);
            if (lane >= o) x += y;
        }
        if (lane == 31) wsum[wid] = x;
        __syncthreads();
        if (wid == 0) {
            int s = wsum[lane];
            #pragma unroll
            for (int o = 1; o < 32; o <<= 1) {
                int y = __shfl_up_sync(0xffffffffu, s, o);
                if (lane >= o) s += y;
            }
            wsum[lane] = s;
        }
        __syncthreads();
        int wprefix = wid ? wsum[wid - 1] : 0;
        int excl = carry + wprefix + (x - tot);
        if (i0 < n) {
            int4 w = make_int4(excl, excl + v.x, excl + s1, excl + s2);
            *(int4*)&g_rowptr[i0] = w;
            *(int4*)&g_cursor[i0] = w;
        }
        carry += wsum[31];
        __syncthreads();
    }
    if (tid == 0) g_rowptr[n] = carry;
}

__global__ void scatter_kernel(const int* __restrict__ ei, int E, int n) {
    int e = blockIdx.x * blockDim.x + threadIdx.x;
    int etot = E + n;
    if (e >= etot) return;
    int src, dst;
    if (e < E) { src = ei[e]; dst = ei[E + e]; }
    else       { src = e - E; dst = e - E; }
    if ((unsigned)dst >= (unsigned)n || (unsigned)src >= (unsigned)n) return;
    int pos = atomicAdd(&g_cursor[dst], 1);
    if (pos < NETOT) g_csrsrc[pos] = src;
}

// ---------------- LAYER 1 GEMM: cp.async double-buffered tf32 ----------------
// A = tf32(x) in g_h1 [M,128]; B(z) = g_w1tf[z] [128,256]; C(z) = xl1/xr1.
// BM=128, BN=64, BK=16; warp tile 32x32 (MT=2, NT=4); 2-stage pipeline.
__global__ void __launch_bounds__(256)
tf32_gemm1_kernel(int M) {
    constexpr int K = DIN, N = F1;
    constexpr int BM = 128, BN = 64, BK = 16;
    constexpr int MT = 2, NT = 4;
    constexpr int AS = BK + 4;    // 20 u32: A bank = (20*lr + lc) % 32, distinct
    constexpr int BS = BN + 8;    // 72 u32: 72 % 32 == 8 -> B bank = 8*lc + lr
    constexpr int NTILE = K / BK; // 8

    __shared__ uint32_t As[2][BM * AS];   // 20 KB
    __shared__ uint32_t Bs[2][BK * BS];   // 9 KB

    const uint32_t* __restrict__ A = (const uint32_t*)g_h1;
    const uint32_t* __restrict__ B = g_w1tf[blockIdx.z];
    float* __restrict__ C = blockIdx.z ? g_xr1 : g_xl1;

    const int bm = blockIdx.y * BM;
    const int bn = blockIdx.x * BN;
    const int tid  = threadIdx.x;
    const int wid  = tid >> 5;
    const int lane = tid & 31;
    const int wm = (wid >> 1) * 32;   // 0,32,64,96
    const int wn = (wid & 1) * 32;    // 0,32
    const int lr = lane >> 2, lc = lane & 3;

    const uint32_t as0 = (uint32_t)__cvta_generic_to_shared(&As[0][0]);
    const uint32_t bs0 = (uint32_t)__cvta_generic_to_shared(&Bs[0][0]);

    // per-thread cp.async source/dest offsets
    const int a_row0 = tid >> 2, a_kc = (tid & 3) << 2;     // chunks tid, tid+256
    const int b_krow = tid >> 4, b_cc = (tid & 15) << 2;

    auto load_tile = [&](int t, int buf) {
        int k0 = t * BK;
        // A: 128x16 = 512 chunks of 16B, 2 per thread
        #pragma unroll
        for (int h = 0; h < 2; h++) {
            int row = a_row0 + h * 64;
            cp_async16(as0 + (uint32_t)(buf * BM * AS + row * AS + a_kc) * 4,
                       A + (size_t)(bm + row) * K + k0 + a_kc);
        }
        // B: 16x64 = 256 chunks of 16B, 1 per thread
        cp_async16(bs0 + (uint32_t)(buf * BK * BS + b_krow * BS + b_cc) * 4,
                   B + (size_t)(k0 + b_krow) * N + bn + b_cc);
        asm volatile("cp.async.commit_group;" ::: "memory");
    };

    float c[MT][NT][4];
    #pragma unroll
    for (int i = 0; i < MT; i++)
        #pragma unroll
        for (int j = 0; j < NT; j++)
            #pragma unroll
            for (int q = 0; q < 4; q++) c[i][j][q] = 0.f;

    load_tile(0, 0);

    #pragma unroll
    for (int t = 0; t < NTILE; t++) {
        const int cur = t & 1;
        if (t < NTILE - 1) {
            load_tile(t + 1, cur ^ 1);
            asm volatile("cp.async.wait_group 1;" ::: "memory");
        } else {
            asm volatile("cp.async.wait_group 0;" ::: "memory");
        }
        __syncthreads();

        const uint32_t* Ab = &As[cur][0];
        const uint32_t* Bb = &Bs[cur][0];
        #pragma unroll
        for (int kk = 0; kk < BK; kk += 8) {
            uint32_t af[MT][4], bf[NT][2];
            #pragma unroll
            for (int mt = 0; mt < MT; mt++) {
                int row = wm + mt * 16 + lr;
                int cA = kk + lc;
                af[mt][0] = Ab[row * AS + cA];
                af[mt][1] = Ab[(row + 8) * AS + cA];
                af[mt][2] = Ab[row * AS + cA + 4];
                af[mt][3] = Ab[(row + 8) * AS + cA + 4];
            }
            #pragma unroll
            for (int nt = 0; nt < NT; nt++) {
                int col = wn + nt * 8 + lr;
                bf[nt][0] = Bb[(kk + lc) * BS + col];
                bf[nt][1] = Bb[(kk + lc + 4) * BS + col];
            }
            #pragma unroll
            for (int mt = 0; mt < MT; mt++)
                #pragma unroll
                for (int nt = 0; nt < NT; nt++)
                    mma_tf32(c[mt][nt], af[mt], bf[nt]);
        }
        __syncthreads();
    }

    #pragma unroll
    for (int mt = 0; mt < MT; mt++) {
        int r0 = bm + wm + mt * 16 + lr;
        int r1 = r0 + 8;
        #pragma unroll
        for (int nt = 0; nt < NT; nt++) {
            int cn = bn + wn + nt * 8 + lc * 2;
            if (r0 < M)
                *(float2*)&C[(size_t)r0 * N + cn] = make_float2(c[mt][nt][0], c[mt][nt][1]);
            if (r1 < M)
                *(float2*)&C[(size_t)r1 * N + cn] = make_float2(c[mt][nt][2], c[mt][nt][3]);
        }
    }
}

// ---------------- LAYER 2 GEMM fused (round-8 proven version) ----------------
__global__ void __launch_bounds__(256)
tf32_gemm2_kernel(const float* __restrict__ Bl,
                  const float* __restrict__ Br, int M) {
    constexpr int K = F1, N = HID;
    constexpr int BM = 128, BK = 32;
    constexpr int NT = 4;
    constexpr int AS = BK + 4;   // 36
    constexpr int BS = N + 8;    // 40

    __shared__ uint32_t As [BM][AS];
    __shared__ uint32_t Bsl[BK][BS];
    __shared__ uint32_t Bsr[BK][BS];

    const float* __restrict__ A = (const float*)g_h1;
    const int bm = blockIdx.y * BM;
    const int tid  = threadIdx.x;
    const int wid  = tid >> 5;
    const int lane = tid & 31;
    const int wm = wid * 16;
    const int lr = lane >> 2, lc = lane & 3;

    float cl[NT][4], cr[NT][4];
    #pragma unroll
    for (int j = 0; j < NT; j++)
        #pragma unroll
        for (int q = 0; q < 4; q++) { cl[j][q] = 0.f; cr[j][q] = 0.f; }

    for (int k0 = 0; k0 < K; k0 += BK) {
        #pragma unroll
        for (int f = tid; f < BM * (BK / 4); f += 256) {
            int r = f >> 3, cv = (f & 7) * 4;
            int gr = bm + r;
            float4 v = (gr < M)
                ? *(const float4*)&A[(size_t)gr * K + k0 + cv]
                : make_float4(0.f, 0.f, 0.f, 0.f);
            As[r][cv]     = f2tf32(v.x);
            As[r][cv + 1] = f2tf32(v.y);
            As[r][cv + 2] = f2tf32(v.z);
            As[r][cv + 3] = f2tf32(v.w);
        }
        #pragma unroll
        for (int f = tid; f < BK * (N / 4); f += 256) {
            int r = f / (N / 4), cv = (f % (N / 4)) * 4;
            float4 vl = *(const float4*)&Bl[(size_t)(k0 + r) * N + cv];
            float4 vr = *(const float4*)&Br[(size_t)(k0 + r) * N + cv];
            Bsl[r][cv]     = f2tf32(vl.x);
            Bsl[r][cv + 1] = f2tf32(vl.y);
            Bsl[r][cv + 2] = f2tf32(vl.z);
            Bsl[r][cv + 3] = f2tf32(vl.w);
            Bsr[r][cv]     = f2tf32(vr.x);
            Bsr[r][cv + 1] = f2tf32(vr.y);
            Bsr[r][cv + 2] = f2tf32(vr.z);
            Bsr[r][cv + 3] = f2tf32(vr.w);
        }
        __syncthreads();
        #pragma unroll
        for (int kk = 0; kk < BK; kk += 8) {
            uint32_t af[4], bfl[NT][2], bfr[NT][2];
            {
                int row = wm + lr;
                int cA = kk + lc;
                af[0] = As[row][cA];
                af[1] = As[row + 8][cA];
                af[2] = As[row][cA + 4];
                af[3] = As[row + 8][cA + 4];
            }
            #pragma unroll
            for (int nt = 0; nt < NT; nt++) {
                int col = nt * 8 + lr;
                bfl[nt][0] = Bsl[kk + lc][col];
                bfl[nt][1] = Bsl[kk + lc + 4][col];
                bfr[nt][0] = Bsr[kk + lc][col];
                bfr[nt][1] = Bsr[kk + lc + 4][col];
            }
            #pragma unroll
            for (int nt = 0; nt < NT; nt++) {
                mma_tf32(cl[nt], af, bfl[nt]);
                mma_tf32(cr[nt], af, bfr[nt]);
            }
        }
        __syncthreads();
    }
    int r0 = bm + wm + lr;
    int r1 = r0 + 8;
    #pragma unroll
    for (int nt = 0; nt < NT; nt++) {
        int cn = nt * 8 + lc * 2;
        if (r0 < M) {
            *(float2*)&g_xl2[(size_t)r0 * N + cn] = make_float2(cl[nt][0], cl[nt][1]);
            *(float2*)&g_xr2[(size_t)r0 * N + cn] = make_float2(cr[nt][0], cr[nt][1]);
        }
        if (r1 < M) {
            *(float2*)&g_xl2[(size_t)r1 * N + cn] = make_float2(cl[nt][2], cl[nt][3]);
            *(float2*)&g_xr2[(size_t)r1 * N + cn] = make_float2(cr[nt][2], cr[nt][3]);
        }
    }
}

// ---------------- layer-1 edge pass: segment softmax + aggregate -------------
__device__ __forceinline__ void gat1_accum(const float4& a, const float4& b,
                                           const float xr[8], const float att[8],
                                           float acc[8], float& den) {
    float xl[8] = {a.x, a.y, a.z, a.w, b.x, b.y, b.z, b.w};
    float p = 0.f;
    #pragma unroll
    for (int i = 0; i < 8; i++) {
        float s = xl[i] + xr[i];
        s = s > 0.f ? s : NEG_SLOPE * s;
        p += s * att[i];
    }
    p += __shfl_xor_sync(0xffffffffu, p, 1);
    p += __shfl_xor_sync(0xffffffffu, p, 2);
    float w = __expf(p);
    den += w;
    #pragma unroll
    for (int i = 0; i < 8; i++) acc[i] += w * xl[i];
}

__global__ void gat1_edge_kernel(const float* __restrict__ att1,
                                 const float* __restrict__ b1, int n) {
    int warp_id = (blockIdx.x * blockDim.x + threadIdx.x) >> 5;
    if (warp_id >= n) return;
    int lane = threadIdx.x & 31;
    int dst  = warp_id;
    int base = (lane >> 2) * 32 + (lane & 3) * 8;  // head*32 + quarter*8

    float xr[8], att[8], acc[8];
    {
        const float4* p0 = (const float4*)&g_xr1[dst * F1 + base];
        float4 a = p0[0], b = p0[1];
        xr[0]=a.x; xr[1]=a.y; xr[2]=a.z; xr[3]=a.w;
        xr[4]=b.x; xr[5]=b.y; xr[6]=b.z; xr[7]=b.w;
        const float4* p1 = (const float4*)&att1[base];
        float4 c = p1[0], d4 = p1[1];
        att[0]=c.x; att[1]=c.y; att[2]=c.z; att[3]=c.w;
        att[4]=d4.x; att[5]=d4.y; att[6]=d4.z; att[7]=d4.w;
    }
    #pragma unroll
    for (int i = 0; i < 8; i++) acc[i] = 0.f;
    float den = 0.f;

    int beg = g_rowptr[dst], end = g_rowptr[dst + 1];
    int e = beg;
    // 2-way unrolled gather (proven best)
    for (; e + 2 <= end; e += 2) {
        int s0 = g_csrsrc[e];
        int s1 = g_csrsrc[e + 1];
        const float4* p0 = (const float4*)&g_xl1[s0 * F1 + base];
        const float4* p1 = (const float4*)&g_xl1[s1 * F1 + base];
        float4 a0 = p0[0], b0 = p0[1];
        float4 a1 = p1[0], b1v = p1[1];
        gat1_accum(a0, b0, xr, att, acc, den);
        gat1_accum(a1, b1v, xr, att, acc, den);
    }
    if (e < end) {
        int s0 = g_csrsrc[e];
        const float4* p0 = (const float4*)&g_xl1[s0 * F1 + base];
        float4 a0 = p0[0], b0 = p0[1];
        gat1_accum(a0, b0, xr, att, acc, den);
    }

    float inv = 1.f / fmaxf(den, 1e-16f);
    const float4* pb = (const float4*)&b1[base];
    float4 bb0 = pb[0], bb1 = pb[1];
    float bb[8] = {bb0.x, bb0.y, bb0.z, bb0.w, bb1.x, bb1.y, bb1.z, bb1.w};
    float o[8];
    #pragma unroll
    for (int i = 0; i < 8; i++) {
        float v = acc[i] * inv + bb[i];
        o[i] = v > 0.f ? v : (__expf(v) - 1.f);   // ELU
    }
    float4* po = (float4*)&g_h1[dst * F1 + base];
    po[0] = make_float4(o[0], o[1], o[2], o[3]);
    po[1] = make_float4(o[4], o[5], o[6], o[7]);
}

// ---------------- layer-2 edge pass + ELU + fused final linear ---------------
__global__ void gat2_edge_kernel(const float* __restrict__ att2,
                                 const float* __restrict__ b2,
                                 const float* __restrict__ Wlin,
                                 const float* __restrict__ blin,
                                 float* __restrict__ out, int n) {
    __shared__ float sh[8 * 32];
    int warp_id = (blockIdx.x * blockDim.x + threadIdx.x) >> 5;
    if (warp_id >= n) return;
    int lane = threadIdx.x & 31;
    int wib  = (threadIdx.x >> 5);
    int dst = warp_id;

    float xr = g_xr2[dst * HID + lane];
    float a  = att2[lane];
    float den = 0.f, acc = 0.f;

    int beg = g_rowptr[dst], end = g_rowptr[dst + 1];
    for (int e = beg; e < end; e++) {
        int src = g_csrsrc[e];
        float xl = g_xl2[src * HID + lane];
        float s = xl + xr;
        s = s > 0.f ? s : NEG_SLOPE * s;
        float p = s * a;
        #pragma unroll
        for (int o = 16; o > 0; o >>= 1)
            p += __shfl_xor_sync(0xffffffffu, p, o);
        float w = __expf(p);
        den += w;
        acc += w * xl;
    }
    float o = acc / fmaxf(den, 1e-16f) + b2[lane];
    float hv = o > 0.f ? o : (__expf(o) - 1.f);   // ELU
    sh[wib * 32 + lane] = hv;
    __syncwarp();
    if (lane < OUTF) {
        float s = blin[lane];
        #pragma unroll
        for (int c = 0; c < HID; c++)
            s += sh[wib * 32 + c] * Wlin[c * OUTF + lane];
        out[dst * OUTF + lane] = s;
    }
}

// ---------------- launch ------------------------------------------------------
extern "C" void kernel_launch(void* const* d_in, const int* in_sizes, int n_in,
                              void* d_out, int out_size) {
    const float* x    = (const float*)d_in[0];
    const int*   ei   = (const int*)d_in[1];     // int32 on device
    const float* W1l  = (const float*)d_in[2];
    const float* W1r  = (const float*)d_in[3];
    const float* att1 = (const float*)d_in[4];
    const float* b1   = (const float*)d_in[5];
    const float* W2l  = (const float*)d_in[6];
    const float* W2r  = (const float*)d_in[7];
    const float* att2 = (const float*)d_in[8];
    const float* b2   = (const float*)d_in[9];
    const float* Wlin = (const float*)d_in[10];
    const float* blin = (const float*)d_in[11];
    float*       out  = (float*)d_out;

    const int n = in_sizes[0] / DIN;        // 50000
    const int E = in_sizes[1] / 2;          // 400000
    const int etot = E + n;

    // single stream; gemm1 is the 4th launch (ncu-profiled slot)
    cvt_w_kernel<<<64, 256>>>(W1l, W1r);                          // k1
    cvt_x_kernel<<<(n * DIN / 4 + 255) / 256, 256>>>(x, n * DIN / 4); // k2
    zero_deg_kernel<<<(n + 255) / 256, 256>>>(n);                 // k3
    {
        dim3 grid(F1 / 64, (n + 127) / 128, 2);
        tf32_gemm1_kernel<<<grid, 256>>>(n);                      // k4 (profiled)
    }
    hist_kernel<<<(etot + 255) / 256, 256>>>(ei, E, n);           // k5
    scan_kernel<<<1, 1024>>>(n);                                  // k6
    scatter_kernel<<<(etot + 255) / 256, 256>>>(ei, E, n);        // k7

    gat1_edge_kernel<<<(n * 32 + 255) / 256, 256>>>(att1, b1, n); // k8

    {
        dim3 grid(1, (n + 127) / 128);
        tf32_gemm2_kernel<<<grid, 256>>>(W2l, W2r, n);            // k9
    }

    gat2_edge_kernel<<<(n * 32 + 255) / 256, 256>>>(att2, b2, Wlin, blin, out, n); // k10
}

// round 12
// speedup vs baseline: 1.0689x; 1.0565x over previous
#include <cuda_runtime.h>
#include <cuda_bf16.h>
#include <math.h>
#include <stdint.h>

// Problem constants (fixed by the dataset)
#define NN    50000
#define NE    400000
#define NETOT (NE + NN)   // with self loops
#define DIN   128
#define HID   32
#define HEADS 8
#define F1    (HEADS * HID)   // 256
#define OUTF  16
#define NEG_SLOPE 0.2f

// ---------------- static device scratch (no allocations allowed) -------------
__device__ float g_xl1[NN * F1];
__device__ float g_xr1[NN * F1];
__device__ float g_h1 [NN * F1];
__device__ float g_xl2[NN * HID];
__device__ float g_xr2[NN * HID];
__device__ int   g_deg[NN];
__device__ int   g_rowptr[NN + 1];
__device__ int   g_cursor[NN];
__device__ int   g_csrsrc[NETOT];

// ---------------- CSR construction ------------------------------------------
__global__ void zero_deg_kernel(int n) {
    int i = blockIdx.x * blockDim.x + threadIdx.x;
    if (i < n) g_deg[i] = 0;
}

__global__ void hist_kernel(const int* __restrict__ ei, int E, int n) {
    int e = blockIdx.x * blockDim.x + threadIdx.x;
    int etot = E + n;
    if (e >= etot) return;
    int dst = (e < E) ? ei[E + e] : (e - E);
    if ((unsigned)dst < (unsigned)n) atomicAdd(&g_deg[dst], 1);
}

// single-block exclusive scan, int4 per thread per iteration
__global__ void scan_kernel(int n) {
    __shared__ int wsum[32];
    int tid  = threadIdx.x;          // blockDim.x == 1024
    int lane = tid & 31, wid = tid >> 5;
    int carry = 0;
    for (int base = 0; base < n; base += 4096) {
        int i0 = base + tid * 4;
        int4 v = make_int4(0, 0, 0, 0);
        if (i0 < n) v = *(const int4*)&g_deg[i0];
        int s1 = v.x + v.y;
        int s2 = s1 + v.z;
        int tot = s2 + v.w;
        int x = tot;
        #pragma unroll
        for (int o = 1; o < 32; o <<= 1) {
            int y = __shfl_up_sync(0xffffffffu, x, o);
            if (lane >= o) x += y;
        }
        if (lane == 31) wsum[wid] = x;
        __syncthreads();
        if (wid == 0) {
            int s = wsum[lane];
            #pragma unroll
            for (int o = 1; o < 32; o <<= 1) {
                int y = __shfl_up_sync(0xffffffffu, s, o);
                if (lane >= o) s += y;
            }
            wsum[lane] = s;
        }
        __syncthreads();
        int wprefix = wid ? wsum[wid - 1] : 0;
        int excl = carry + wprefix + (x - tot);
        if (i0 < n) {
            int4 w = make_int4(excl, excl + v.x, excl + s1, excl + s2);
            *(int4*)&g_rowptr[i0] = w;
            *(int4*)&g_cursor[i0] = w;
        }
        carry += wsum[31];
        __syncthreads();
    }
    if (tid == 0) g_rowptr[n] = carry;
}

__global__ void scatter_kernel(const int* __restrict__ ei, int E, int n) {
    int e = blockIdx.x * blockDim.x + threadIdx.x;
    int etot = E + n;
    if (e >= etot) return;
    int src, dst;
    if (e < E) { src = ei[e]; dst = ei[E + e]; }
    else       { src = e - E; dst = e - E; }
    if ((unsigned)dst >= (unsigned)n || (unsigned)src >= (unsigned)n) return;
    int pos = atomicAdd(&g_cursor[dst], 1);
    if (pos < NETOT) g_csrsrc[pos] = src;
}

// ---------------- tf32 tensor-core GEMMs -------------------------------------
__device__ __forceinline__ uint32_t f2tf32(float x) {
    uint32_t r;
    asm("cvt.rna.tf32.f32 %0, %1;" : "=r"(r) : "f"(x));
    return r;
}

__device__ __forceinline__ void mma_tf32(float c[4], const uint32_t a[4],
                                         const uint32_t b[2]) {
    asm volatile(
        "mma.sync.aligned.m16n8k8.row.col.f32.tf32.tf32.f32 "
        "{%0,%1,%2,%3}, {%4,%5,%6,%7}, {%8,%9}, {%0,%1,%2,%3};"
        : "+f"(c[0]), "+f"(c[1]), "+f"(c[2]), "+f"(c[3])
        : "r"(a[0]), "r"(a[1]), "r"(a[2]), "r"(a[3]), "r"(b[0]), "r"(b[1]));
}

// LAYER 1: A = x [M,128], B(z) = W1l/W1r [128,256], C(z) = g_xl1/g_xr1
// 128x128 block tile, 64x32 warp tile (MT=4, NT=4). SMEM holds tf32 bits
// (converted at store) in the conflict-free scalar layout.  (round-8 proven)
__global__ void __launch_bounds__(256, 2)
tf32_gemm1_kernel(const float* __restrict__ A,
                  const float* __restrict__ Bl,
                  const float* __restrict__ Br, int M) {
    constexpr int K = DIN, N = F1;
    constexpr int BM = 128, BN = 128, BK = 32;
    constexpr int MT = 4, NT = 4, WN = 4;
    constexpr int AS = BK + 4;    // 36 u32: bank = 4*row + k (all distinct)
    constexpr int BS = BN + 8;    // 136 u32: 136 % 32 == 8 -> bank = 8*k + col

    __shared__ uint32_t As[BM][AS];
    __shared__ uint32_t Bs[BK][BS];

    const float* __restrict__ B = blockIdx.z ? Br : Bl;
    float* __restrict__ C = blockIdx.z ? g_xr1 : g_xl1;

    const int bm = blockIdx.y * BM;
    const int bn = blockIdx.x * BN;
    const int tid  = threadIdx.x;
    const int wid  = tid >> 5;
    const int lane = tid & 31;
    const int wm = (wid / WN) * (MT * 16);   // 0 or 64
    const int wn = (wid % WN) * (NT * 8);    // 0,32,64,96
    const int lr = lane >> 2, lc = lane & 3;

    float c[MT][NT][4];
    #pragma unroll
    for (int i = 0; i < MT; i++)
        #pragma unroll
        for (int j = 0; j < NT; j++)
            #pragma unroll
            for (int q = 0; q < 4; q++) c[i][j][q] = 0.f;

    for (int k0 = 0; k0 < K; k0 += BK) {
        #pragma unroll
        for (int f = tid; f < BM * (BK / 4); f += 256) {
            int r = f >> 3, cv = (f & 7) * 4;
            int gr = bm + r;
            float4 v = (gr < M)
                ? *(const float4*)&A[(size_t)gr * K + k0 + cv]
                : make_float4(0.f, 0.f, 0.f, 0.f);
            As[r][cv]     = f2tf32(v.x);
            As[r][cv + 1] = f2tf32(v.y);
            As[r][cv + 2] = f2tf32(v.z);
            As[r][cv + 3] = f2tf32(v.w);
        }
        #pragma unroll
        for (int f = tid; f < BK * (BN / 4); f += 256) {
            int r = f / (BN / 4), cv = (f % (BN / 4)) * 4;
            float4 v = *(const float4*)&B[(size_t)(k0 + r) * N + bn + cv];
            Bs[r][cv]     = f2tf32(v.x);
            Bs[r][cv + 1] = f2tf32(v.y);
            Bs[r][cv + 2] = f2tf32(v.z);
            Bs[r][cv + 3] = f2tf32(v.w);
        }
        __syncthreads();
        #pragma unroll
        for (int kk = 0; kk < BK; kk += 8) {
            uint32_t af[MT][4], bf[NT][2];
            #pragma unroll
            for (int mt = 0; mt < MT; mt++) {
                int row = wm + mt * 16 + lr;
                int cA = kk + lc;
                af[mt][0] = As[row][cA];
                af[mt][1] = As[row + 8][cA];
                af[mt][2] = As[row][cA + 4];
                af[mt][3] = As[row + 8][cA + 4];
            }
            #pragma unroll
            for (int nt = 0; nt < NT; nt++) {
                int col = wn + nt * 8 + lr;
                bf[nt][0] = Bs[kk + lc][col];
                bf[nt][1] = Bs[kk + lc + 4][col];
            }
            #pragma unroll
            for (int mt = 0; mt < MT; mt++)
                #pragma unroll
                for (int nt = 0; nt < NT; nt++)
                    mma_tf32(c[mt][nt], af[mt], bf[nt]);
        }
        __syncthreads();
    }
    #pragma unroll
    for (int mt = 0; mt < MT; mt++) {
        int r0 = bm + wm + mt * 16 + lr;
        int r1 = r0 + 8;
        #pragma unroll
        for (int nt = 0; nt < NT; nt++) {
            int cn = bn + wn + nt * 8 + lc * 2;
            if (r0 < M)
                *(float2*)&C[(size_t)r0 * N + cn] = make_float2(c[mt][nt][0], c[mt][nt][1]);
            if (r1 < M)
                *(float2*)&C[(size_t)r1 * N + cn] = make_float2(c[mt][nt][2], c[mt][nt][3]);
        }
    }
}

// LAYER 2 fused: A = g_h1 [M,256]; computes BOTH xl2 and xr2 in one pass.
__global__ void __launch_bounds__(256)
tf32_gemm2_kernel(const float* __restrict__ Bl,
                  const float* __restrict__ Br, int M) {
    constexpr int K = F1, N = HID;
    constexpr int BM = 128, BK = 32;
    constexpr int NT = 4;
    constexpr int AS = BK + 4;   // 36
    constexpr int BS = N + 8;    // 40

    __shared__ uint32_t As [BM][AS];
    __shared__ uint32_t Bsl[BK][BS];
    __shared__ uint32_t Bsr[BK][BS];

    const float* __restrict__ A = (const float*)g_h1;
    const int bm = blockIdx.y * BM;
    const int tid  = threadIdx.x;
    const int wid  = tid >> 5;
    const int lane = tid & 31;
    const int wm = wid * 16;
    const int lr = lane >> 2, lc = lane & 3;

    float cl[NT][4], cr[NT][4];
    #pragma unroll
    for (int j = 0; j < NT; j++)
        #pragma unroll
        for (int q = 0; q < 4; q++) { cl[j][q] = 0.f; cr[j][q] = 0.f; }

    for (int k0 = 0; k0 < K; k0 += BK) {
        #pragma unroll
        for (int f = tid; f < BM * (BK / 4); f += 256) {
            int r = f >> 3, cv = (f & 7) * 4;
            int gr = bm + r;
            float4 v = (gr < M)
                ? *(const float4*)&A[(size_t)gr * K + k0 + cv]
                : make_float4(0.f, 0.f, 0.f, 0.f);
            As[r][cv]     = f2tf32(v.x);
            As[r][cv + 1] = f2tf32(v.y);
            As[r][cv + 2] = f2tf32(v.z);
            As[r][cv + 3] = f2tf32(v.w);
        }
        #pragma unroll
        for (int f = tid; f < BK * (N / 4); f += 256) {
            int r = f / (N / 4), cv = (f % (N / 4)) * 4;
            float4 vl = *(const float4*)&Bl[(size_t)(k0 + r) * N + cv];
            float4 vr = *(const float4*)&Br[(size_t)(k0 + r) * N + cv];
            Bsl[r][cv]     = f2tf32(vl.x);
            Bsl[r][cv + 1] = f2tf32(vl.y);
            Bsl[r][cv + 2] = f2tf32(vl.z);
            Bsl[r][cv + 3] = f2tf32(vl.w);
            Bsr[r][cv]     = f2tf32(vr.x);
            Bsr[r][cv + 1] = f2tf32(vr.y);
            Bsr[r][cv + 2] = f2tf32(vr.z);
            Bsr[r][cv + 3] = f2tf32(vr.w);
        }
        __syncthreads();
        #pragma unroll
        for (int kk = 0; kk < BK; kk += 8) {
            uint32_t af[4], bfl[NT][2], bfr[NT][2];
            {
                int row = wm + lr;
                int cA = kk + lc;
                af[0] = As[row][cA];
                af[1] = As[row + 8][cA];
                af[2] = As[row][cA + 4];
                af[3] = As[row + 8][cA + 4];
            }
            #pragma unroll
            for (int nt = 0; nt < NT; nt++) {
                int col = nt * 8 + lr;
                bfl[nt][0] = Bsl[kk + lc][col];
                bfl[nt][1] = Bsl[kk + lc + 4][col];
                bfr[nt][0] = Bsr[kk + lc][col];
                bfr[nt][1] = Bsr[kk + lc + 4][col];
            }
            #pragma unroll
            for (int nt = 0; nt < NT; nt++) {
                mma_tf32(cl[nt], af, bfl[nt]);
                mma_tf32(cr[nt], af, bfr[nt]);
            }
        }
        __syncthreads();
    }
    int r0 = bm + wm + lr;
    int r1 = r0 + 8;
    #pragma unroll
    for (int nt = 0; nt < NT; nt++) {
        int cn = nt * 8 + lc * 2;
        if (r0 < M) {
            *(float2*)&g_xl2[(size_t)r0 * N + cn] = make_float2(cl[nt][0], cl[nt][1]);
            *(float2*)&g_xr2[(size_t)r0 * N + cn] = make_float2(cr[nt][0], cr[nt][1]);
        }
        if (r1 < M) {
            *(float2*)&g_xl2[(size_t)r1 * N + cn] = make_float2(cl[nt][2], cl[nt][3]);
            *(float2*)&g_xr2[(size_t)r1 * N + cn] = make_float2(cr[nt][2], cr[nt][3]);
        }
    }
}

// ---------------- layer-1 edge pass: segment softmax + aggregate -------------
// ONE WARP = ONE CTA = ONE DST NODE (32-thread blocks kill the CTA-tail:
// slots recycle per node instead of waiting for the slowest of 8 warps).
__device__ __forceinline__ void gat1_accum(const float4& a, const float4& b,
                                           const float xr[8], const float att[8],
                                           float acc[8], float& den) {
    float xl[8] = {a.x, a.y, a.z, a.w, b.x, b.y, b.z, b.w};
    float p = 0.f;
    #pragma unroll
    for (int i = 0; i < 8; i++) {
        float s = xl[i] + xr[i];
        s = s > 0.f ? s : NEG_SLOPE * s;
        p += s * att[i];
    }
    p += __shfl_xor_sync(0xffffffffu, p, 1);
    p += __shfl_xor_sync(0xffffffffu, p, 2);
    float w = __expf(p);
    den += w;
    #pragma unroll
    for (int i = 0; i < 8; i++) acc[i] += w * xl[i];
}

__global__ void __launch_bounds__(32)
gat1_edge_kernel(const float* __restrict__ att1,
                 const float* __restrict__ b1, int n) {
    int dst = blockIdx.x;
    if (dst >= n) return;
    int lane = threadIdx.x;
    int base = (lane >> 2) * 32 + (lane & 3) * 8;  // head*32 + quarter*8

    float xr[8], att[8], acc[8];
    {
        const float4* p0 = (const float4*)&g_xr1[dst * F1 + base];
        float4 a = p0[0], b = p0[1];
        xr[0]=a.x; xr[1]=a.y; xr[2]=a.z; xr[3]=a.w;
        xr[4]=b.x; xr[5]=b.y; xr[6]=b.z; xr[7]=b.w;
        const float4* p1 = (const float4*)&att1[base];
        float4 c = p1[0], d4 = p1[1];
        att[0]=c.x; att[1]=c.y; att[2]=c.z; att[3]=c.w;
        att[4]=d4.x; att[5]=d4.y; att[6]=d4.z; att[7]=d4.w;
    }
    #pragma unroll
    for (int i = 0; i < 8; i++) acc[i] = 0.f;
    float den = 0.f;

    int beg = g_rowptr[dst], end = g_rowptr[dst + 1];
    int e = beg;
    // 2-way unrolled gather (proven best)
    for (; e + 2 <= end; e += 2) {
        int s0 = g_csrsrc[e];
        int s1 = g_csrsrc[e + 1];
        const float4* p0 = (const float4*)&g_xl1[s0 * F1 + base];
        const float4* p1 = (const float4*)&g_xl1[s1 * F1 + base];
        float4 a0 = p0[0], b0 = p0[1];
        float4 a1 = p1[0], b1v = p1[1];
        gat1_accum(a0, b0, xr, att, acc, den);
        gat1_accum(a1, b1v, xr, att, acc, den);
    }
    if (e < end) {
        int s0 = g_csrsrc[e];
        const float4* p0 = (const float4*)&g_xl1[s0 * F1 + base];
        float4 a0 = p0[0], b0 = p0[1];
        gat1_accum(a0, b0, xr, att, acc, den);
    }

    float inv = 1.f / fmaxf(den, 1e-16f);
    const float4* pb = (const float4*)&b1[base];
    float4 bb0 = pb[0], bb1 = pb[1];
    float bb[8] = {bb0.x, bb0.y, bb0.z, bb0.w, bb1.x, bb1.y, bb1.z, bb1.w};
    float o[8];
    #pragma unroll
    for (int i = 0; i < 8; i++) {
        float v = acc[i] * inv + bb[i];
        o[i] = v > 0.f ? v : (__expf(v) - 1.f);   // ELU
    }
    float4* po = (float4*)&g_h1[dst * F1 + base];
    po[0] = make_float4(o[0], o[1], o[2], o[3]);
    po[1] = make_float4(o[4], o[5], o[6], o[7]);
}

// ---------------- layer-2 edge pass + ELU + fused final linear ---------------
__global__ void __launch_bounds__(32)
gat2_edge_kernel(const float* __restrict__ att2,
                 const float* __restrict__ b2,
                 const float* __restrict__ Wlin,
                 const float* __restrict__ blin,
                 float* __restrict__ out, int n) {
    __shared__ float sh[32];
    int dst = blockIdx.x;
    if (dst >= n) return;
    int lane = threadIdx.x;

    float xr = g_xr2[dst * HID + lane];
    float a  = att2[lane];
    float den = 0.f, acc = 0.f;

    int beg = g_rowptr[dst], end = g_rowptr[dst + 1];
    int e = beg;
    for (; e + 2 <= end; e += 2) {
        int s0 = g_csrsrc[e];
        int s1 = g_csrsrc[e + 1];
        float xl0 = g_xl2[s0 * HID + lane];
        float xl1 = g_xl2[s1 * HID + lane];
        float t0 = xl0 + xr; t0 = t0 > 0.f ? t0 : NEG_SLOPE * t0;
        float t1 = xl1 + xr; t1 = t1 > 0.f ? t1 : NEG_SLOPE * t1;
        float p0 = t0 * a, p1 = t1 * a;
        #pragma unroll
        for (int o = 16; o > 0; o >>= 1) {
            p0 += __shfl_xor_sync(0xffffffffu, p0, o);
            p1 += __shfl_xor_sync(0xffffffffu, p1, o);
        }
        float w0 = __expf(p0), w1 = __expf(p1);
        den += w0; acc += w0 * xl0;
        den += w1; acc += w1 * xl1;
    }
    if (e < end) {
        int src = g_csrsrc[e];
        float xl = g_xl2[src * HID + lane];
        float s = xl + xr;
        s = s > 0.f ? s : NEG_SLOPE * s;
        float p = s * a;
        #pragma unroll
        for (int o = 16; o > 0; o >>= 1)
            p += __shfl_xor_sync(0xffffffffu, p, o);
        float w = __expf(p);
        den += w;
        acc += w * xl;
    }
    float o = acc / fmaxf(den, 1e-16f) + b2[lane];
    float hv = o > 0.f ? o : (__expf(o) - 1.f);   // ELU
    sh[lane] = hv;
    __syncwarp();
    if (lane < OUTF) {
        float s = blin[lane];
        #pragma unroll
        for (int c = 0; c < HID; c++)
            s += sh[c] * Wlin[c * OUTF + lane];
        out[dst * OUTF + lane] = s;
    }
}

// ---------------- launch ------------------------------------------------------
extern "C" void kernel_launch(void* const* d_in, const int* in_sizes, int n_in,
                              void* d_out, int out_size) {
    const float* x    = (const float*)d_in[0];
    const int*   ei   = (const int*)d_in[1];     // int32 on device
    const float* W1l  = (const float*)d_in[2];
    const float* W1r  = (const float*)d_in[3];
    const float* att1 = (const float*)d_in[4];
    const float* b1   = (const float*)d_in[5];
    const float* W2l  = (const float*)d_in[6];
    const float* W2r  = (const float*)d_in[7];
    const float* att2 = (const float*)d_in[8];
    const float* b2   = (const float*)d_in[9];
    const float* Wlin = (const float*)d_in[10];
    const float* blin = (const float*)d_in[11];
    float*       out  = (float*)d_out;

    const int n = in_sizes[0] / DIN;        // 50000
    const int E = in_sizes[1] / 2;          // 400000
    const int etot = E + n;

    // launches ordered so the profiled slot (4th) captures gemm1.
    zero_deg_kernel<<<(n + 255) / 256, 256>>>(n);                 // k1
    hist_kernel<<<(etot + 255) / 256, 256>>>(ei, E, n);           // k2
    scan_kernel<<<1, 1024>>>(n);                                  // k3
    {
        dim3 grid(F1 / 128, (n + 127) / 128, 2);
        tf32_gemm1_kernel<<<grid, 256>>>(x, W1l, W1r, n);         // k4 (profiled)
    }
    scatter_kernel<<<(etot + 255) / 256, 256>>>(ei, E, n);        // k5

    gat1_edge_kernel<<<n, 32>>>(att1, b1, n);                     // k6

    {
        dim3 grid(1, (n + 127) / 128);
        tf32_gemm2_kernel<<<grid, 256>>>(W2l, W2r, n);            // k7
    }

    gat2_edge_kernel<<<n, 32>>>(att2, b2, Wlin, blin, out, n);    // k8
}